// round 10
// baseline (speedup 1.0000x reference)
#include <cuda_runtime.h>
#include <cuda_fp16.h>

#define NN 50000
#define NE 800000
#define D 128
#define OUTW4 160        // 640 floats / 4 per output row

// ---- scratch (__device__ globals; no allocations allowed) ----
__device__ unsigned long long g_pack[NN];       // (count << 40) | fixpoint32(sum w)
__device__ float              g_deg[NN];        // dinv
__device__ int                g_alloc;          // bump allocator
__device__ int                g_rank[NE];       // per-edge rank within its col
__device__ unsigned long long g_seg[NN];        // packed (cnt << 32) | start
__device__ unsigned long long g_csr[NE];        // packed (ew_bits << 32) | (row * 32)
__device__ float              g_gsum[D];        // global feature sum
__device__ __align__(16) __half g_m0[NN * D];   // fp16 mirror ping (z = dinv*x)
__device__ __align__(16) __half g_m1[NN * D];   // fp16 mirror pong

// ---------------------------------------------------------------------------
__global__ void zero_kernel() {
    int i = blockIdx.x * blockDim.x + threadIdx.x;
    if (i < NN) g_pack[i] = 0ull;
    if (i < D)  g_gsum[i] = 0.0f;
    if (i == 0) g_alloc = 0;
}

// ONE packed atomic per edge: degree sum (fixed point) + count; return = rank.
__global__ void deg_kernel(const int* __restrict__ ei,
                           const float* __restrict__ ew) {
    int e = blockIdx.x * blockDim.x + threadIdx.x;
    if (e >= NE) return;
    int col = ei[NE + e];
    float w = ew[e];
    unsigned long long v =
        (1ull << 40) | (unsigned long long)((double)w * 4294967296.0);
    unsigned long long old = atomicAdd(&g_pack[col], v);
    g_rank[e] = (int)(old >> 40);
}

// dinv + segment bump-alloc (warp-aggregated atomic)
__global__ void alloc_kernel() {
    int i = blockIdx.x * 256 + threadIdx.x;
    int lane = threadIdx.x & 31;
    int cnt = 0;
    if (i < NN) {
        unsigned long long p = g_pack[i];
        cnt = (int)(p >> 40);
        double d = (double)(p & ((1ull << 40) - 1ull)) * (1.0 / 4294967296.0);
        g_deg[i] = (d > 0.0) ? rsqrtf((float)d) : 0.0f;
    }
    int iv = cnt;
    #pragma unroll
    for (int s = 1; s < 32; s <<= 1) {
        int t = __shfl_up_sync(0xffffffffu, iv, s);
        if (lane >= s) iv += t;
    }
    int base = 0;
    if (lane == 31) base = atomicAdd(&g_alloc, iv);
    base = __shfl_sync(0xffffffffu, base, 31);
    int start = base + iv - cnt;
    if (i < NN)
        g_seg[i] = ((unsigned long long)(unsigned int)cnt << 32) |
                   (unsigned int)start;
}

// scatter: dinv folded OUT of edge weight (store raw ew).
// random refs per edge: seg[col] read + csr store only.
__global__ void scatter_kernel(const int* __restrict__ ei,
                               const float* __restrict__ ew) {
    int e = blockIdx.x * blockDim.x + threadIdx.x;
    if (e >= NE) return;
    int row = ei[e];
    int col = ei[NE + e];
    int pos = (int)(g_seg[col] & 0xffffffffu) + g_rank[e];
    g_csr[pos] = ((unsigned long long)__float_as_uint(ew[e]) << 32) |
                 (unsigned int)(row * 32);           // row offset in uint2 units
}

// copy x -> out slab0 (fp32) + fp16 mirror m0 (z = dinv*x) + column sums.
// dinv fetched COALESCED up-front (2 loads/warp), distributed via shfl.
__global__ void copy_mean_kernel(const float* __restrict__ x, float* __restrict__ out) {
    int lane = threadIdx.x & 31;
    int wrp  = blockIdx.x * 8 + (threadIdx.x >> 5);
    int r0 = wrp * 64;
    if (r0 >= NN) return;
    const float4* x4 = (const float4*)x;
    float4* out4 = (float4*)out;
    uint2* m0 = (uint2*)g_m0;
    float di0 = (r0 + lane      < NN) ? g_deg[r0 + lane]      : 0.0f;
    float di1 = (r0 + 32 + lane < NN) ? g_deg[r0 + 32 + lane] : 0.0f;
    float4 s = make_float4(0.f, 0.f, 0.f, 0.f);

    #pragma unroll 4
    for (int j = 0; j < 32; j++) {
        int r = r0 + j;
        if (r >= NN) break;
        float di = __shfl_sync(0xffffffffu, di0, j);
        float4 v = x4[r * 32 + lane];
        out4[(long long)r * OUTW4 + lane] = v;
        __half2 h0 = __floats2half2_rn(di * v.x, di * v.y);
        __half2 h1 = __floats2half2_rn(di * v.z, di * v.w);
        uint2 mv; mv.x = *(unsigned int*)&h0; mv.y = *(unsigned int*)&h1;
        m0[r * 32 + lane] = mv;
        s.x += v.x; s.y += v.y; s.z += v.z; s.w += v.w;
    }
    #pragma unroll 4
    for (int j = 0; j < 32; j++) {
        int r = r0 + 32 + j;
        if (r >= NN) break;
        float di = __shfl_sync(0xffffffffu, di1, j);
        float4 v = x4[r * 32 + lane];
        out4[(long long)r * OUTW4 + lane] = v;
        __half2 h0 = __floats2half2_rn(di * v.x, di * v.y);
        __half2 h1 = __floats2half2_rn(di * v.z, di * v.w);
        uint2 mv; mv.x = *(unsigned int*)&h0; mv.y = *(unsigned int*)&h1;
        m0[r * 32 + lane] = mv;
        s.x += v.x; s.y += v.y; s.z += v.z; s.w += v.w;
    }
    atomicAdd(&g_gsum[lane * 4 + 0], s.x);
    atomicAdd(&g_gsum[lane * 4 + 1], s.y);
    atomicAdd(&g_gsum[lane * 4 + 2], s.z);
    atomicAdd(&g_gsum[lane * 4 + 3], s.w);
}

// warp-per-node gather: s_i = sum ew_e * z_row ; slab = dinv_i*s ; mirror = dinv_i^2*s
// which = 0: in=m0, mir=m1 | 1: in=m1, mir=m0 | 2: in=m0, final (+ mean slab)
__global__ void hop_kernel(float* __restrict__ out, int out_off4, int which) {
    int lane = threadIdx.x & 31;
    int node = blockIdx.x * 8 + (threadIdx.x >> 5);
    if (node >= NN) return;
    const uint2* __restrict__ in2 =
        (which == 1) ? (const uint2*)g_m1 : (const uint2*)g_m0;
    unsigned long long seg = g_seg[node];
    int start = (int)(seg & 0xffffffffu);
    int cnt   = (int)(seg >> 32);
    int end   = start + cnt;
    float di  = g_deg[node];                         // issue early, consumed at tail
    float4 acc = make_float4(0.f, 0.f, 0.f, 0.f);

    int e = start;
    for (; e + 8 <= end; e += 8) {
        unsigned long long p[8];
        uint2 v[8];
        #pragma unroll
        for (int k = 0; k < 8; k++) p[k] = __ldg(&g_csr[e + k]);
        #pragma unroll
        for (int k = 0; k < 8; k++) v[k] = __ldg(&in2[(int)(p[k] & 0xffffffffu) + lane]);
        #pragma unroll
        for (int k = 0; k < 8; k++) {
            float w = __uint_as_float((unsigned int)(p[k] >> 32));
            float2 a = __half22float2(*(__half2*)&v[k].x);
            float2 b = __half22float2(*(__half2*)&v[k].y);
            acc.x += w * a.x; acc.y += w * a.y; acc.z += w * b.x; acc.w += w * b.y;
        }
    }
    for (; e + 4 <= end; e += 4) {
        unsigned long long p[4];
        uint2 v[4];
        #pragma unroll
        for (int k = 0; k < 4; k++) p[k] = __ldg(&g_csr[e + k]);
        #pragma unroll
        for (int k = 0; k < 4; k++) v[k] = __ldg(&in2[(int)(p[k] & 0xffffffffu) + lane]);
        #pragma unroll
        for (int k = 0; k < 4; k++) {
            float w = __uint_as_float((unsigned int)(p[k] >> 32));
            float2 a = __half22float2(*(__half2*)&v[k].x);
            float2 b = __half22float2(*(__half2*)&v[k].y);
            acc.x += w * a.x; acc.y += w * a.y; acc.z += w * b.x; acc.w += w * b.y;
        }
    }
    for (; e < end; e++) {
        unsigned long long p = __ldg(&g_csr[e]);
        uint2 v = __ldg(&in2[(int)(p & 0xffffffffu) + lane]);
        float w = __uint_as_float((unsigned int)(p >> 32));
        float2 a = __half22float2(*(__half2*)&v.x);
        float2 b = __half22float2(*(__half2*)&v.y);
        acc.x += w * a.x; acc.y += w * a.y; acc.z += w * b.x; acc.w += w * b.y;
    }

    float4 xo = make_float4(di * acc.x, di * acc.y, di * acc.z, di * acc.w);
    ((float4*)out)[(long long)node * OUTW4 + out_off4 + lane] = xo;
    if (which != 2) {
        uint2* mir2 = (which == 0) ? (uint2*)g_m1 : (uint2*)g_m0;
        __half2 h0 = __floats2half2_rn(di * xo.x, di * xo.y);
        __half2 h1 = __floats2half2_rn(di * xo.z, di * xo.w);
        uint2 mv; mv.x = *(unsigned int*)&h0; mv.y = *(unsigned int*)&h1;
        mir2[node * 32 + lane] = mv;
    } else {
        const float inv = 1.0f / (float)NN;
        float4 g = make_float4(g_gsum[lane * 4 + 0] * inv, g_gsum[lane * 4 + 1] * inv,
                               g_gsum[lane * 4 + 2] * inv, g_gsum[lane * 4 + 3] * inv);
        ((float4*)out)[(long long)node * OUTW4 + 128 + lane] = g;
    }
}

// ---------------------------------------------------------------------------
extern "C" void kernel_launch(void* const* d_in, const int* in_sizes, int n_in,
                              void* d_out, int out_size) {
    const float* x  = (const float*)d_in[0];
    const int*   ei = (const int*)d_in[1];
    const float* ew = (const float*)d_in[2];
    float* out = (float*)d_out;

    zero_kernel<<<(NN + 255) / 256, 256>>>();
    deg_kernel<<<(NE + 255) / 256, 256>>>(ei, ew);  // 1 packed atomic/edge + rank
    alloc_kernel<<<(NN + 255) / 256, 256>>>();      // dinv + segment bump-alloc
    scatter_kernel<<<(NE + 255) / 256, 256>>>(ei, ew);  // atomic-free, no deg reads
    copy_mean_kernel<<<98, 256>>>(x, out);          // 784 warps x 64 rows

    hop_kernel<<<(NN + 7) / 8, 256>>>(out, 32, 0);  // m0 -> slab1, mirror m1
    hop_kernel<<<(NN + 7) / 8, 256>>>(out, 64, 1);  // m1 -> slab2, mirror m0
    hop_kernel<<<(NN + 7) / 8, 256>>>(out, 96, 2);  // m0 -> slab3, + mean slab
}

// round 11
// speedup vs baseline: 1.1216x; 1.1216x over previous
#include <cuda_runtime.h>
#include <cuda_fp16.h>

#define NN 50000
#define NE 800000
#define D 128
#define OUTW4 160        // 640 floats / 4 per output row

// ---- scratch (__device__ globals; no allocations allowed) ----
__device__ unsigned long long g_pack[NN];       // (count << 40) | fixpoint32(sum w)
__device__ float              g_deg[NN];        // dinv
__device__ int                g_alloc;          // bump allocator
__device__ int                g_rank[NE];       // per-edge rank within its col
__device__ uint4              g_seg[NN];        // {start, cnt, dinv_bits, 0}
__device__ unsigned long long g_csr[NE];        // packed (w_bits << 32) | (row * 32)
__device__ float              g_gsum[D];        // global feature sum
__device__ __align__(16) __half g_m0[NN * D];   // fp16 mirror ping
__device__ __align__(16) __half g_m1[NN * D];   // fp16 mirror pong

// ---------------------------------------------------------------------------
__global__ void zero_kernel() {
    int i = blockIdx.x * blockDim.x + threadIdx.x;
    if (i < NN) g_pack[i] = 0ull;
    if (i < D)  g_gsum[i] = 0.0f;
    if (i == 0) g_alloc = 0;
}

// ONE packed atomic per edge: degree sum (fixed point) + count; return = rank.
// edge_index is int32 (JAX demotes int64 without x64 flag)
__global__ void deg_kernel(const int* __restrict__ ei,
                           const float* __restrict__ ew) {
    int e = blockIdx.x * blockDim.x + threadIdx.x;
    if (e >= NE) return;
    int col = ei[NE + e];
    float w = ew[e];
    unsigned long long v =
        (1ull << 40) | (unsigned long long)((double)w * 4294967296.0);
    unsigned long long old = atomicAdd(&g_pack[col], v);
    g_rank[e] = (int)(old >> 40);
}

// dinv + segment bump-alloc; seg carries {start, cnt, dinv} in one 16B word
__global__ void alloc_kernel() {
    int i = blockIdx.x * 256 + threadIdx.x;
    int lane = threadIdx.x & 31;
    int cnt = 0;
    float dinv = 0.0f;
    if (i < NN) {
        unsigned long long p = g_pack[i];
        cnt = (int)(p >> 40);
        double d = (double)(p & ((1ull << 40) - 1ull)) * (1.0 / 4294967296.0);
        dinv = (d > 0.0) ? rsqrtf((float)d) : 0.0f;
        g_deg[i] = dinv;
    }
    int iv = cnt;
    #pragma unroll
    for (int s = 1; s < 32; s <<= 1) {
        int t = __shfl_up_sync(0xffffffffu, iv, s);
        if (lane >= s) iv += t;
    }
    int base = 0;
    if (lane == 31) base = atomicAdd(&g_alloc, iv);
    base = __shfl_sync(0xffffffffu, base, 31);
    int start = base + iv - cnt;
    if (i < NN)
        g_seg[i] = make_uint4((unsigned int)start, (unsigned int)cnt,
                              __float_as_uint(dinv), 0u);
}

// scatter: stores FULL normalized weight (R8 semantics).
// random refs per edge: seg16B(col) [gives start + dinv_col], deg[row], store.
__global__ void scatter_kernel(const int* __restrict__ ei,
                               const float* __restrict__ ew) {
    int e = blockIdx.x * blockDim.x + threadIdx.x;
    if (e >= NE) return;
    int row = ei[e];
    int col = ei[NE + e];
    uint4 s4 = g_seg[col];                           // one 16B random read
    float w = g_deg[row] * ew[e] * __uint_as_float(s4.z);
    int pos = (int)s4.x + g_rank[e];
    g_csr[pos] = ((unsigned long long)__float_as_uint(w) << 32) |
                 (unsigned int)(row * 32);           // row offset in uint2 units
}

// copy x -> out slab0 (fp32) + fp16 mirror m0 + column-sum atomics  (R8 form)
__global__ void copy_mean_kernel(const float* __restrict__ x, float* __restrict__ out) {
    int lane = threadIdx.x & 31;
    int wrp  = blockIdx.x * 8 + (threadIdx.x >> 5);
    int r0 = wrp * 64;
    if (r0 >= NN) return;
    int r1 = min(r0 + 64, NN);
    const float4* x4 = (const float4*)x;
    float4* out4 = (float4*)out;
    uint2* m0 = (uint2*)g_m0;
    float4 s = make_float4(0.f, 0.f, 0.f, 0.f);
    for (int r = r0; r < r1; r++) {
        float4 v = x4[r * 32 + lane];
        out4[(long long)r * OUTW4 + lane] = v;
        __half2 h0 = __floats2half2_rn(v.x, v.y);
        __half2 h1 = __floats2half2_rn(v.z, v.w);
        uint2 mv;
        mv.x = *(unsigned int*)&h0;
        mv.y = *(unsigned int*)&h1;
        m0[r * 32 + lane] = mv;
        s.x += v.x; s.y += v.y; s.z += v.z; s.w += v.w;
    }
    atomicAdd(&g_gsum[lane * 4 + 0], s.x);
    atomicAdd(&g_gsum[lane * 4 + 1], s.y);
    atomicAdd(&g_gsum[lane * 4 + 2], s.z);
    atomicAdd(&g_gsum[lane * 4 + 3], s.w);
}

// warp-per-node gather over fp16 mirror; fp32 accumulate; 8-deep pipeline (R8 form).
// which = 0: in=m0, mir=m1 | 1: in=m1, mir=m0 | 2: in=m0, final (+ mean slab)
__global__ void hop_kernel(float* __restrict__ out, int out_off4, int which) {
    int lane = threadIdx.x & 31;
    int node = blockIdx.x * 8 + (threadIdx.x >> 5);
    if (node >= NN) return;
    const uint2* __restrict__ in2 =
        (which == 1) ? (const uint2*)g_m1 : (const uint2*)g_m0;
    uint4 seg = g_seg[node];
    int start = (int)seg.x;
    int cnt   = (int)seg.y;
    int end   = start + cnt;
    float4 acc = make_float4(0.f, 0.f, 0.f, 0.f);

    int e = start;
    for (; e + 8 <= end; e += 8) {
        unsigned long long p[8];
        uint2 v[8];
        #pragma unroll
        for (int k = 0; k < 8; k++) p[k] = __ldg(&g_csr[e + k]);
        #pragma unroll
        for (int k = 0; k < 8; k++) v[k] = __ldg(&in2[(int)(p[k] & 0xffffffffu) + lane]);
        #pragma unroll
        for (int k = 0; k < 8; k++) {
            float w = __uint_as_float((unsigned int)(p[k] >> 32));
            float2 a = __half22float2(*(__half2*)&v[k].x);
            float2 b = __half22float2(*(__half2*)&v[k].y);
            acc.x += w * a.x; acc.y += w * a.y; acc.z += w * b.x; acc.w += w * b.y;
        }
    }
    for (; e + 4 <= end; e += 4) {
        unsigned long long p[4];
        uint2 v[4];
        #pragma unroll
        for (int k = 0; k < 4; k++) p[k] = __ldg(&g_csr[e + k]);
        #pragma unroll
        for (int k = 0; k < 4; k++) v[k] = __ldg(&in2[(int)(p[k] & 0xffffffffu) + lane]);
        #pragma unroll
        for (int k = 0; k < 4; k++) {
            float w = __uint_as_float((unsigned int)(p[k] >> 32));
            float2 a = __half22float2(*(__half2*)&v[k].x);
            float2 b = __half22float2(*(__half2*)&v[k].y);
            acc.x += w * a.x; acc.y += w * a.y; acc.z += w * b.x; acc.w += w * b.y;
        }
    }
    for (; e < end; e++) {
        unsigned long long p = __ldg(&g_csr[e]);
        uint2 v = __ldg(&in2[(int)(p & 0xffffffffu) + lane]);
        float w = __uint_as_float((unsigned int)(p >> 32));
        float2 a = __half22float2(*(__half2*)&v.x);
        float2 b = __half22float2(*(__half2*)&v.y);
        acc.x += w * a.x; acc.y += w * a.y; acc.z += w * b.x; acc.w += w * b.y;
    }

    ((float4*)out)[(long long)node * OUTW4 + out_off4 + lane] = acc;
    if (which != 2) {
        uint2* mir2 = (which == 0) ? (uint2*)g_m1 : (uint2*)g_m0;
        __half2 h0 = __floats2half2_rn(acc.x, acc.y);
        __half2 h1 = __floats2half2_rn(acc.z, acc.w);
        uint2 mv;
        mv.x = *(unsigned int*)&h0;
        mv.y = *(unsigned int*)&h1;
        mir2[node * 32 + lane] = mv;
    } else {
        const float inv = 1.0f / (float)NN;
        float4 g = make_float4(g_gsum[lane * 4 + 0] * inv, g_gsum[lane * 4 + 1] * inv,
                               g_gsum[lane * 4 + 2] * inv, g_gsum[lane * 4 + 3] * inv);
        ((float4*)out)[(long long)node * OUTW4 + 128 + lane] = g;
    }
}

// ---------------------------------------------------------------------------
extern "C" void kernel_launch(void* const* d_in, const int* in_sizes, int n_in,
                              void* d_out, int out_size) {
    const float* x  = (const float*)d_in[0];
    const int*   ei = (const int*)d_in[1];
    const float* ew = (const float*)d_in[2];
    float* out = (float*)d_out;

    zero_kernel<<<(NN + 255) / 256, 256>>>();
    deg_kernel<<<(NE + 255) / 256, 256>>>(ei, ew);  // 1 packed atomic/edge + rank
    alloc_kernel<<<(NN + 255) / 256, 256>>>();      // dinv + segment bump-alloc
    scatter_kernel<<<(NE + 255) / 256, 256>>>(ei, ew);  // atomic-free, 16B seg read
    copy_mean_kernel<<<98, 256>>>(x, out);          // 784 warps x 64 rows

    hop_kernel<<<(NN + 7) / 8, 256>>>(out, 32, 0);  // m0 -> slab1, mirror m1
    hop_kernel<<<(NN + 7) / 8, 256>>>(out, 64, 1);  // m1 -> slab2, mirror m0
    hop_kernel<<<(NN + 7) / 8, 256>>>(out, 96, 2);  // m0 -> slab3, + mean slab
}

// round 12
// speedup vs baseline: 1.2373x; 1.1032x over previous
#include <cuda_runtime.h>
#include <cuda_fp16.h>

#define NN 50000
#define NE 800000
#define D 128
#define OUTW4 160        // 640 floats / 4 per output row

// ---- scratch (__device__ globals; no allocations allowed) ----
__device__ unsigned long long g_pack[NN];       // (count << 40) | fixpoint32(sum w)
__device__ float              g_deg[NN];        // dinv
__device__ int                g_alloc;          // bump allocator
__device__ int                g_rank[NE];       // per-edge rank within its col
__device__ uint4              g_seg[NN];        // {start, cnt, dinv_bits, 0}
__device__ unsigned long long g_csr[NE];        // packed (w_bits << 32) | (row * 32)
__device__ float              g_gsum[D];        // global feature sum
__device__ __align__(16) __half g_m0[NN * D];   // fp16 mirror ping
__device__ __align__(16) __half g_m1[NN * D];   // fp16 mirror pong

// ---------------------------------------------------------------------------
__global__ void zero_kernel() {
    int i = blockIdx.x * blockDim.x + threadIdx.x;
    if (i < NN) g_pack[i] = 0ull;
    if (i < D)  g_gsum[i] = 0.0f;
    if (i == 0) g_alloc = 0;
}

// ONE packed atomic per edge: degree sum (fixed point) + count; return = rank.
// Two edges per thread (vectorized index/weight loads).
__global__ void deg_kernel(const int* __restrict__ ei,
                           const float* __restrict__ ew) {
    int t = blockIdx.x * blockDim.x + threadIdx.x;
    int e0 = t * 2;
    if (e0 >= NE) return;
    int2   c2 = *(const int2*)&ei[NE + e0];
    float2 w2 = *(const float2*)&ew[e0];
    {
        unsigned long long v =
            (1ull << 40) | (unsigned long long)((double)w2.x * 4294967296.0);
        unsigned long long old = atomicAdd(&g_pack[c2.x], v);
        g_rank[e0] = (int)(old >> 40);
    }
    {
        unsigned long long v =
            (1ull << 40) | (unsigned long long)((double)w2.y * 4294967296.0);
        unsigned long long old = atomicAdd(&g_pack[c2.y], v);
        g_rank[e0 + 1] = (int)(old >> 40);
    }
}

// dinv + segment bump-alloc; seg carries {start, cnt, dinv} in one 16B word
__global__ void alloc_kernel() {
    int i = blockIdx.x * 256 + threadIdx.x;
    int lane = threadIdx.x & 31;
    int cnt = 0;
    float dinv = 0.0f;
    if (i < NN) {
        unsigned long long p = g_pack[i];
        cnt = (int)(p >> 40);
        double d = (double)(p & ((1ull << 40) - 1ull)) * (1.0 / 4294967296.0);
        dinv = (d > 0.0) ? rsqrtf((float)d) : 0.0f;
        g_deg[i] = dinv;
    }
    int iv = cnt;
    #pragma unroll
    for (int s = 1; s < 32; s <<= 1) {
        int t = __shfl_up_sync(0xffffffffu, iv, s);
        if (lane >= s) iv += t;
    }
    int base = 0;
    if (lane == 31) base = atomicAdd(&g_alloc, iv);
    base = __shfl_sync(0xffffffffu, base, 31);
    int start = base + iv - cnt;
    if (i < NN)
        g_seg[i] = make_uint4((unsigned int)start, (unsigned int)cnt,
                              __float_as_uint(dinv), 0u);
}

// scatter: stores FULL normalized weight.
// random refs per edge: seg16B(col) [start + dinv_col], deg[row], store.
__global__ void scatter_kernel(const int* __restrict__ ei,
                               const float* __restrict__ ew) {
    int e = blockIdx.x * blockDim.x + threadIdx.x;
    if (e >= NE) return;
    int row = ei[e];
    int col = ei[NE + e];
    uint4 s4 = g_seg[col];                           // one 16B random read
    float w = g_deg[row] * ew[e] * __uint_as_float(s4.z);
    int pos = (int)s4.x + g_rank[e];
    g_csr[pos] = ((unsigned long long)__float_as_uint(w) << 32) |
                 (unsigned int)(row * 32);           // row offset in uint2 units
}

// copy x -> out slab0 (fp32, STREAMING store) + fp16 mirror m0 + column sums
__global__ void copy_mean_kernel(const float* __restrict__ x, float* __restrict__ out) {
    int lane = threadIdx.x & 31;
    int wrp  = blockIdx.x * 8 + (threadIdx.x >> 5);
    int r0 = wrp * 64;
    if (r0 >= NN) return;
    int r1 = min(r0 + 64, NN);
    const float4* x4 = (const float4*)x;
    float4* out4 = (float4*)out;
    uint2* m0 = (uint2*)g_m0;
    float4 s = make_float4(0.f, 0.f, 0.f, 0.f);
    for (int r = r0; r < r1; r++) {
        float4 v = x4[r * 32 + lane];
        __stcs(&out4[(long long)r * OUTW4 + lane], v);   // evict-first: keep L2 for mirrors
        __half2 h0 = __floats2half2_rn(v.x, v.y);
        __half2 h1 = __floats2half2_rn(v.z, v.w);
        uint2 mv;
        mv.x = *(unsigned int*)&h0;
        mv.y = *(unsigned int*)&h1;
        m0[r * 32 + lane] = mv;
        s.x += v.x; s.y += v.y; s.z += v.z; s.w += v.w;
    }
    atomicAdd(&g_gsum[lane * 4 + 0], s.x);
    atomicAdd(&g_gsum[lane * 4 + 1], s.y);
    atomicAdd(&g_gsum[lane * 4 + 2], s.z);
    atomicAdd(&g_gsum[lane * 4 + 3], s.w);
}

// warp-per-node gather over fp16 mirror; fp32 accumulate; 8-deep pipeline.
// Slab writes are STREAMING (never re-read); mirror writes stay cached (reused next hop).
// which = 0: in=m0, mir=m1 | 1: in=m1, mir=m0 | 2: in=m0, final (+ mean slab)
__global__ void hop_kernel(float* __restrict__ out, int out_off4, int which) {
    int lane = threadIdx.x & 31;
    int node = blockIdx.x * 8 + (threadIdx.x >> 5);
    if (node >= NN) return;
    const uint2* __restrict__ in2 =
        (which == 1) ? (const uint2*)g_m1 : (const uint2*)g_m0;
    uint4 seg = g_seg[node];
    int start = (int)seg.x;
    int cnt   = (int)seg.y;
    int end   = start + cnt;
    float4 acc = make_float4(0.f, 0.f, 0.f, 0.f);

    int e = start;
    for (; e + 8 <= end; e += 8) {
        unsigned long long p[8];
        uint2 v[8];
        #pragma unroll
        for (int k = 0; k < 8; k++) p[k] = __ldg(&g_csr[e + k]);
        #pragma unroll
        for (int k = 0; k < 8; k++) v[k] = __ldg(&in2[(int)(p[k] & 0xffffffffu) + lane]);
        #pragma unroll
        for (int k = 0; k < 8; k++) {
            float w = __uint_as_float((unsigned int)(p[k] >> 32));
            float2 a = __half22float2(*(__half2*)&v[k].x);
            float2 b = __half22float2(*(__half2*)&v[k].y);
            acc.x += w * a.x; acc.y += w * a.y; acc.z += w * b.x; acc.w += w * b.y;
        }
    }
    for (; e + 4 <= end; e += 4) {
        unsigned long long p[4];
        uint2 v[4];
        #pragma unroll
        for (int k = 0; k < 4; k++) p[k] = __ldg(&g_csr[e + k]);
        #pragma unroll
        for (int k = 0; k < 4; k++) v[k] = __ldg(&in2[(int)(p[k] & 0xffffffffu) + lane]);
        #pragma unroll
        for (int k = 0; k < 4; k++) {
            float w = __uint_as_float((unsigned int)(p[k] >> 32));
            float2 a = __half22float2(*(__half2*)&v[k].x);
            float2 b = __half22float2(*(__half2*)&v[k].y);
            acc.x += w * a.x; acc.y += w * a.y; acc.z += w * b.x; acc.w += w * b.y;
        }
    }
    for (; e < end; e++) {
        unsigned long long p = __ldg(&g_csr[e]);
        uint2 v = __ldg(&in2[(int)(p & 0xffffffffu) + lane]);
        float w = __uint_as_float((unsigned int)(p >> 32));
        float2 a = __half22float2(*(__half2*)&v.x);
        float2 b = __half22float2(*(__half2*)&v.y);
        acc.x += w * a.x; acc.y += w * a.y; acc.z += w * b.x; acc.w += w * b.y;
    }

    __stcs(&((float4*)out)[(long long)node * OUTW4 + out_off4 + lane], acc);
    if (which != 2) {
        uint2* mir2 = (which == 0) ? (uint2*)g_m1 : (uint2*)g_m0;
        __half2 h0 = __floats2half2_rn(acc.x, acc.y);
        __half2 h1 = __floats2half2_rn(acc.z, acc.w);
        uint2 mv;
        mv.x = *(unsigned int*)&h0;
        mv.y = *(unsigned int*)&h1;
        mir2[node * 32 + lane] = mv;                 // cached: read next hop
    } else {
        const float inv = 1.0f / (float)NN;
        float4 g = make_float4(g_gsum[lane * 4 + 0] * inv, g_gsum[lane * 4 + 1] * inv,
                               g_gsum[lane * 4 + 2] * inv, g_gsum[lane * 4 + 3] * inv);
        __stcs(&((float4*)out)[(long long)node * OUTW4 + 128 + lane], g);
    }
}

// ---------------------------------------------------------------------------
extern "C" void kernel_launch(void* const* d_in, const int* in_sizes, int n_in,
                              void* d_out, int out_size) {
    const float* x  = (const float*)d_in[0];
    const int*   ei = (const int*)d_in[1];
    const float* ew = (const float*)d_in[2];
    float* out = (float*)d_out;

    zero_kernel<<<(NN + 255) / 256, 256>>>();
    deg_kernel<<<(NE / 2 + 255) / 256, 256>>>(ei, ew);  // 2 edges/thread
    alloc_kernel<<<(NN + 255) / 256, 256>>>();
    scatter_kernel<<<(NE + 255) / 256, 256>>>(ei, ew);
    copy_mean_kernel<<<98, 256>>>(x, out);

    hop_kernel<<<(NN + 7) / 8, 256>>>(out, 32, 0);  // m0 -> slab1, mirror m1
    hop_kernel<<<(NN + 7) / 8, 256>>>(out, 64, 1);  // m1 -> slab2, mirror m0
    hop_kernel<<<(NN + 7) / 8, 256>>>(out, 96, 2);  // m0 -> slab3, + mean slab
}